// round 1
// baseline (speedup 1.0000x reference)
#include <cuda_runtime.h>
#include <math.h>

// Problem constants
#define NN 100000
#define EE 1600000
#define DD 128

// ---------------- scratch (static device globals; no allocation) -------------
__device__ float g_buf0[NN * DD];
__device__ float g_buf1[NN * DD];
__device__ float g_agg[NN * DD];

__device__ int   g_src[EE];
__device__ int   g_dst[EE];
__device__ int   g_col[EE];

__device__ int   g_cnt[NN];
__device__ int   g_rowptr[NN + 1];
__device__ int   g_wcur[NN];
__device__ float g_invdeg[NN];

__device__ int   g_tmp[NN];       // per-block exclusive scan
__device__ int   g_bsum[128];
__device__ int   g_bbase[128];
__device__ int   g_is64;

// ---------------- edge dtype probe + convert --------------------------------
__global__ void k_probe(const long long* __restrict__ p) {
    // If the data is really int32 pairs, interpreting as int64 yields values
    // >= 2^32 with overwhelming probability across 256 samples.
    int t = threadIdx.x;
    long long v = p[t];
    int bad = (v < 0 || v >= NN) ? 1 : 0;
    __shared__ int anybad;
    if (t == 0) anybad = 0;
    __syncthreads();
    if (__ballot_sync(0xffffffffu, bad)) {
        if ((t & 31) == 0) atomicOr(&anybad, 1);
    }
    __syncthreads();
    if (t == 0) g_is64 = anybad ? 0 : 1;
}

__global__ void k_convert(const void* __restrict__ ei) {
    int e = blockIdx.x * blockDim.x + threadIdx.x;
    if (e >= EE) return;
    if (g_is64) {
        const long long* p = (const long long*)ei;
        g_src[e] = (int)p[e];
        g_dst[e] = (int)p[EE + e];
    } else {
        const int* p = (const int*)ei;
        g_src[e] = p[e];
        g_dst[e] = p[EE + e];
    }
}

// ---------------- CSR build ---------------------------------------------------
__global__ void k_zero_cnt() {
    int i = blockIdx.x * blockDim.x + threadIdx.x;
    if (i < NN) g_cnt[i] = 0;
}

__global__ void k_hist() {
    int e = blockIdx.x * blockDim.x + threadIdx.x;
    if (e < EE) atomicAdd(&g_cnt[g_dst[e]], 1);
}

__global__ void k_scan1() {
    __shared__ int s[1024];
    int tid = threadIdx.x;
    int gid = blockIdx.x * 1024 + tid;
    int v = (gid < NN) ? g_cnt[gid] : 0;
    s[tid] = v;
    __syncthreads();
    for (int off = 1; off < 1024; off <<= 1) {
        int t = (tid >= off) ? s[tid - off] : 0;
        __syncthreads();
        s[tid] += t;
        __syncthreads();
    }
    int incl = s[tid];
    if (gid < NN) g_tmp[gid] = incl - v;   // exclusive within block
    if (tid == 1023) g_bsum[blockIdx.x] = incl;
}

__global__ void k_scan2(int nb) {
    if (threadIdx.x == 0 && blockIdx.x == 0) {
        int run = 0;
        for (int i = 0; i < nb; i++) { g_bbase[i] = run; run += g_bsum[i]; }
    }
}

__global__ void k_scan3() {
    int i = blockIdx.x * blockDim.x + threadIdx.x;
    if (i < NN) {
        int rp = g_tmp[i] + g_bbase[i >> 10];
        g_rowptr[i] = rp;
        g_wcur[i] = rp;
        int c = g_cnt[i];
        g_invdeg[i] = 1.0f / (float)(c > 1 ? c : 1);
        if (i == 0) g_rowptr[NN] = EE;
    }
}

__global__ void k_scatter() {
    int e = blockIdx.x * blockDim.x + threadIdx.x;
    if (e < EE) {
        int d = g_dst[e];
        int pos = atomicAdd(&g_wcur[d], 1);
        g_col[pos] = g_src[e];
    }
}

// ---------------- mean aggregation: one warp per node ------------------------
__global__ void k_aggregate(const float* __restrict__ hin) {
    int warp = (blockIdx.x * blockDim.x + threadIdx.x) >> 5;
    int lane = threadIdx.x & 31;
    if (warp >= NN) return;
    int beg = g_rowptr[warp];
    int end = g_rowptr[warp + 1];
    float4 acc = make_float4(0.f, 0.f, 0.f, 0.f);
    int j = beg;
    for (; j + 1 < end; j += 2) {
        int s0 = __ldg(&g_col[j]);
        int s1 = __ldg(&g_col[j + 1]);
        float4 v0 = *reinterpret_cast<const float4*>(hin + (size_t)s0 * DD + lane * 4);
        float4 v1 = *reinterpret_cast<const float4*>(hin + (size_t)s1 * DD + lane * 4);
        acc.x += v0.x; acc.y += v0.y; acc.z += v0.z; acc.w += v0.w;
        acc.x += v1.x; acc.y += v1.y; acc.z += v1.z; acc.w += v1.w;
    }
    if (j < end) {
        int s0 = __ldg(&g_col[j]);
        float4 v0 = *reinterpret_cast<const float4*>(hin + (size_t)s0 * DD + lane * 4);
        acc.x += v0.x; acc.y += v0.y; acc.z += v0.z; acc.w += v0.w;
    }
    float id = g_invdeg[warp];
    acc.x *= id; acc.y *= id; acc.z *= id; acc.w *= id;
    *reinterpret_cast<float4*>(g_agg + (size_t)warp * DD + lane * 4) = acc;
}

// ---------------- fused GEMM + bias + LayerNorm + ELU / L2-norm --------------
// out[n,:] = act( LN( mean[n,:] @ Wl + x[n,:] @ Wr + bl ) )
// Tile: 64 rows x 128 cols, 256 threads, each thread: 8 rows x 4 cols.
// mode 0: ELU epilogue; mode 1: row L2-normalize epilogue.
__global__ __launch_bounds__(256) void k_gemm_ln(
    const float* __restrict__ A0,   // mean aggregate [N,128]
    const float* __restrict__ A1,   // node features  [N,128]
    const float* __restrict__ Wl, const float* __restrict__ bl,
    const float* __restrict__ Wr,
    const float* __restrict__ g, const float* __restrict__ b,
    float* __restrict__ out, int mode)
{
    __shared__ float As[64][32];    // [m][kk]
    __shared__ float Bs[32][128];   // [kk][c]

    int tid = threadIdx.x;
    int row0 = blockIdx.x * 64;
    int mgrp = tid >> 5;            // warp id: rows 8*mgrp .. 8*mgrp+7
    int lane = tid & 31;
    int c0 = lane * 4;

    float acc[8][4];
#pragma unroll
    for (int r = 0; r < 8; r++)
#pragma unroll
        for (int jj = 0; jj < 4; jj++) acc[r][jj] = 0.f;

    for (int kt = 0; kt < 8; kt++) {
        const float* Asrc = (kt < 4) ? A0 : A1;
        const float* Wsrc = (kt < 4) ? Wl : Wr;
        int koff = (kt & 3) * 32;   // k offset within the 128-dim half

        // A tile: 64 x 32 (512 float4 loads, 2 per thread)
#pragma unroll
        for (int it = 0; it < 2; it++) {
            int i = tid + it * 256;
            int m = i >> 3;
            int k4 = (i & 7) * 4;
            int row = row0 + m;
            float4 v = make_float4(0.f, 0.f, 0.f, 0.f);
            if (row < NN)
                v = *reinterpret_cast<const float4*>(Asrc + (size_t)row * DD + koff + k4);
            *reinterpret_cast<float4*>(&As[m][k4]) = v;
        }
        // B tile: 32 x 128 (1024 float4... actually 32*128/4=1024 floats -> 256 float4? no:
        // 32*128 = 4096 floats = 1024 float4, 4 per thread)
#pragma unroll
        for (int it = 0; it < 4; it++) {
            int i = tid + it * 256;
            int kk = i >> 5;
            int cc = (i & 31) * 4;
            float4 v = *reinterpret_cast<const float4*>(Wsrc + (size_t)(koff + kk) * DD + cc);
            *reinterpret_cast<float4*>(&Bs[kk][cc]) = v;
        }
        __syncthreads();

#pragma unroll
        for (int kk = 0; kk < 32; kk++) {
            float bf0 = Bs[kk][c0 + 0];
            float bf1 = Bs[kk][c0 + 1];
            float bf2 = Bs[kk][c0 + 2];
            float bf3 = Bs[kk][c0 + 3];
#pragma unroll
            for (int r = 0; r < 8; r++) {
                float a = As[mgrp * 8 + r][kk];   // warp-uniform broadcast
                acc[r][0] = fmaf(a, bf0, acc[r][0]);
                acc[r][1] = fmaf(a, bf1, acc[r][1]);
                acc[r][2] = fmaf(a, bf2, acc[r][2]);
                acc[r][3] = fmaf(a, bf3, acc[r][3]);
            }
        }
        __syncthreads();
    }

    // epilogue
    float blv[4], gv[4], bv[4];
#pragma unroll
    for (int jj = 0; jj < 4; jj++) {
        blv[jj] = __ldg(&bl[c0 + jj]);
        gv[jj]  = __ldg(&g[c0 + jj]);
        bv[jj]  = __ldg(&b[c0 + jj]);
    }

#pragma unroll
    for (int r = 0; r < 8; r++) {
        int row = row0 + mgrp * 8 + r;
        float s1 = 0.f, s2 = 0.f;
#pragma unroll
        for (int jj = 0; jj < 4; jj++) {
            float a = acc[r][jj] + blv[jj];
            acc[r][jj] = a;
            s1 += a;
            s2 += a * a;
        }
#pragma unroll
        for (int off = 16; off > 0; off >>= 1) {
            s1 += __shfl_xor_sync(0xffffffffu, s1, off);
            s2 += __shfl_xor_sync(0xffffffffu, s2, off);
        }
        float mu  = s1 * (1.0f / 128.0f);
        float var = s2 * (1.0f / 128.0f) - mu * mu;
        float rstd = rsqrtf(var + 1e-5f);
        float y[4];
#pragma unroll
        for (int jj = 0; jj < 4; jj++)
            y[jj] = (acc[r][jj] - mu) * rstd * gv[jj] + bv[jj];

        if (mode == 0) {
#pragma unroll
            for (int jj = 0; jj < 4; jj++)
                y[jj] = (y[jj] > 0.f) ? y[jj] : expm1f(y[jj]);
        } else {
            float q = y[0]*y[0] + y[1]*y[1] + y[2]*y[2] + y[3]*y[3];
#pragma unroll
            for (int off = 16; off > 0; off >>= 1)
                q += __shfl_xor_sync(0xffffffffu, q, off);
            float nrm = sqrtf(q);
            float sc = 1.0f / fmaxf(nrm, 1e-12f);
#pragma unroll
            for (int jj = 0; jj < 4; jj++) y[jj] *= sc;
        }
        if (row < NN)
            *reinterpret_cast<float4*>(out + (size_t)row * DD + c0) =
                make_float4(y[0], y[1], y[2], y[3]);
    }
}

// ---------------- launch ------------------------------------------------------
extern "C" void kernel_launch(void* const* d_in, const int* in_sizes, int n_in,
                              void* d_out, int out_size) {
    const float* x = (const float*)d_in[0];
    const void* ei = d_in[1];

    float* buf0; cudaGetSymbolAddress((void**)&buf0, g_buf0);
    float* buf1; cudaGetSymbolAddress((void**)&buf1, g_buf1);
    float* agg;  cudaGetSymbolAddress((void**)&agg,  g_agg);

    const int TB = 256;
    const int EBLK = (EE + TB - 1) / TB;
    const int NBLK = (NN + TB - 1) / TB;
    const int SCAN_NB = (NN + 1023) / 1024;

    // edge dtype probe + int32 conversion
    k_probe<<<1, 256>>>((const long long*)ei);
    k_convert<<<EBLK, TB>>>(ei);

    // CSR build
    k_zero_cnt<<<NBLK, TB>>>();
    k_hist<<<EBLK, TB>>>();
    k_scan1<<<SCAN_NB, 1024>>>();
    k_scan2<<<1, 32>>>(SCAN_NB);
    k_scan3<<<NBLK, TB>>>();
    k_scatter<<<EBLK, TB>>>();

    const int AGG_BLK = (NN * 32 + TB - 1) / TB;
    const int GEMM_BLK = (NN + 63) / 64;

    for (int l = 0; l < 3; l++) {
        const float* hin = (l == 0) ? x : ((l == 1) ? buf0 : buf1);
        float* hout = (l == 0) ? buf0 : ((l == 1) ? buf1 : (float*)d_out);
        const float* Wl = (const float*)d_in[2 + 5 * l + 0];
        const float* bl = (const float*)d_in[2 + 5 * l + 1];
        const float* Wr = (const float*)d_in[2 + 5 * l + 2];
        const float* gg = (const float*)d_in[2 + 5 * l + 3];
        const float* bb = (const float*)d_in[2 + 5 * l + 4];

        k_aggregate<<<AGG_BLK, TB>>>(hin);
        k_gemm_ln<<<GEMM_BLK, TB>>>(agg, hin, Wl, bl, Wr, gg, bb, hout,
                                    (l < 2) ? 0 : 1);
    }
}

// round 3
// speedup vs baseline: 1.2840x; 1.2840x over previous
#include <cuda_runtime.h>
#include <cuda_bf16.h>
#include <math.h>
#include <cstdint>

#define NN 100000
#define EE 1600000
#define DD 128
#define NROWS4 ((NN * DD) / 4)

// ---------------- scratch (static device globals; no allocation) -------------
__device__ __align__(16) float g_buf0[NN * DD];   // layer0 fp32 out
__device__ __align__(16) float g_buf1[NN * DD];   // layer1 fp32 out

// bf16 hi/lo split activations (GEMM inputs)
__device__ __align__(16) __nv_bfloat16 g_h0hi[NN * DD];
__device__ __align__(16) __nv_bfloat16 g_h0lo[NN * DD];
__device__ __align__(16) __nv_bfloat16 g_h1hi[NN * DD];
__device__ __align__(16) __nv_bfloat16 g_h1lo[NN * DD];
__device__ __align__(16) __nv_bfloat16 g_ahi[NN * DD];
__device__ __align__(16) __nv_bfloat16 g_alo[NN * DD];

__device__ int   g_src[EE];
__device__ int   g_dst[EE];
__device__ int   g_col[EE];

__device__ int   g_cnt[NN];
__device__ int   g_rowptr[NN + 1];
__device__ int   g_wcur[NN];
__device__ float g_invdeg[NN];

__device__ int   g_tmp[NN];
__device__ int   g_bsum[128];
__device__ int   g_bbase[128];
__device__ int   g_is64;

// pre-split transposed weights: [n=128][k=256] bf16, hi/lo
__device__ __align__(16) __nv_bfloat16 g_wt_hi[128 * 256];
__device__ __align__(16) __nv_bfloat16 g_wt_lo[128 * 256];

// ================= helpers =====================================================
__device__ __forceinline__ uint32_t smem_u32(const void* p) {
    uint32_t a;
    asm("{ .reg .u64 t; cvta.to.shared.u64 t, %1; cvt.u32.u64 %0, t; }" : "=r"(a) : "l"(p));
    return a;
}
__device__ __forceinline__ void ldm_x4(uint32_t* r, uint32_t addr) {
    asm volatile("ldmatrix.sync.aligned.m8n8.x4.shared.b16 {%0,%1,%2,%3}, [%4];"
                 : "=r"(r[0]), "=r"(r[1]), "=r"(r[2]), "=r"(r[3]) : "r"(addr));
}
__device__ __forceinline__ void mma16816(float* c, const uint32_t* a, uint32_t b0, uint32_t b1) {
    asm volatile(
        "mma.sync.aligned.m16n8k16.row.col.f32.bf16.bf16.f32 "
        "{%0,%1,%2,%3},{%4,%5,%6,%7},{%8,%9},{%0,%1,%2,%3};"
        : "+f"(c[0]), "+f"(c[1]), "+f"(c[2]), "+f"(c[3])
        : "r"(a[0]), "r"(a[1]), "r"(a[2]), "r"(a[3]), "r"(b0), "r"(b1));
}
__device__ __forceinline__ uint32_t pack_hi(float a, float b) {
    __nv_bfloat16 ha = __float2bfloat16(a), hb = __float2bfloat16(b);
    return (uint32_t)__bfloat16_as_ushort(ha) | ((uint32_t)__bfloat16_as_ushort(hb) << 16);
}
__device__ __forceinline__ void split2(float a, float b, uint32_t& hi, uint32_t& lo) {
    __nv_bfloat16 ha = __float2bfloat16(a), hb = __float2bfloat16(b);
    float ra = a - __bfloat162float(ha), rb = b - __bfloat162float(hb);
    __nv_bfloat16 la = __float2bfloat16(ra), lb = __float2bfloat16(rb);
    hi = (uint32_t)__bfloat16_as_ushort(ha) | ((uint32_t)__bfloat16_as_ushort(hb) << 16);
    lo = (uint32_t)__bfloat16_as_ushort(la) | ((uint32_t)__bfloat16_as_ushort(lb) << 16);
}

// ---------------- edge dtype probe + convert ----------------------------------
__global__ void k_probe(const long long* __restrict__ p) {
    int t = threadIdx.x;
    long long v = p[t];
    int bad = (v < 0 || v >= NN) ? 1 : 0;
    __shared__ int anybad;
    if (t == 0) anybad = 0;
    __syncthreads();
    if (__ballot_sync(0xffffffffu, bad)) {
        if ((t & 31) == 0) atomicOr(&anybad, 1);
    }
    __syncthreads();
    if (t == 0) g_is64 = anybad ? 0 : 1;
}
__global__ void k_convert(const void* __restrict__ ei) {
    int e = blockIdx.x * blockDim.x + threadIdx.x;
    if (e >= EE) return;
    if (g_is64) {
        const long long* p = (const long long*)ei;
        g_src[e] = (int)p[e];
        g_dst[e] = (int)p[EE + e];
    } else {
        const int* p = (const int*)ei;
        g_src[e] = p[e];
        g_dst[e] = p[EE + e];
    }
}

// ---------------- CSR build ----------------------------------------------------
__global__ void k_zero_cnt() {
    int i = blockIdx.x * blockDim.x + threadIdx.x;
    if (i < NN) g_cnt[i] = 0;
}
__global__ void k_hist() {
    int e = blockIdx.x * blockDim.x + threadIdx.x;
    if (e < EE) atomicAdd(&g_cnt[g_dst[e]], 1);
}
__global__ void k_scan1() {
    __shared__ int s[1024];
    int tid = threadIdx.x;
    int gid = blockIdx.x * 1024 + tid;
    int v = (gid < NN) ? g_cnt[gid] : 0;
    s[tid] = v;
    __syncthreads();
    for (int off = 1; off < 1024; off <<= 1) {
        int t = (tid >= off) ? s[tid - off] : 0;
        __syncthreads();
        s[tid] += t;
        __syncthreads();
    }
    int incl = s[tid];
    if (gid < NN) g_tmp[gid] = incl - v;
    if (tid == 1023) g_bsum[blockIdx.x] = incl;
}
__global__ void k_scan2(int nb) {
    if (threadIdx.x == 0 && blockIdx.x == 0) {
        int run = 0;
        for (int i = 0; i < nb; i++) { g_bbase[i] = run; run += g_bsum[i]; }
    }
}
__global__ void k_scan3() {
    int i = blockIdx.x * blockDim.x + threadIdx.x;
    if (i < NN) {
        int rp = g_tmp[i] + g_bbase[i >> 10];
        g_rowptr[i] = rp;
        g_wcur[i] = rp;
        int c = g_cnt[i];
        g_invdeg[i] = 1.0f / (float)(c > 1 ? c : 1);
        if (i == 0) g_rowptr[NN] = EE;
    }
}
__global__ void k_scatter() {
    int e = blockIdx.x * blockDim.x + threadIdx.x;
    if (e < EE) {
        int d = g_dst[e];
        int pos = atomicAdd(&g_wcur[d], 1);
        g_col[pos] = g_src[e];
    }
}

// ---------------- split x to bf16 hi/lo ----------------------------------------
__global__ void k_split_x(const float* __restrict__ x,
                          __nv_bfloat16* __restrict__ hi, __nv_bfloat16* __restrict__ lo) {
    int i = blockIdx.x * blockDim.x + threadIdx.x;
    if (i >= NROWS4) return;
    float4 v = ((const float4*)x)[i];
    uint2 uh, ul;
    split2(v.x, v.y, uh.x, ul.x);
    split2(v.z, v.w, uh.y, ul.y);
    ((uint2*)hi)[i] = uh;
    ((uint2*)lo)[i] = ul;
}

// ---------------- mean aggregation: one warp per node, bf16 hi/lo out ---------
__global__ void k_aggregate(const float* __restrict__ hin) {
    int warp = (blockIdx.x * blockDim.x + threadIdx.x) >> 5;
    int lane = threadIdx.x & 31;
    if (warp >= NN) return;
    int beg = g_rowptr[warp];
    int end = g_rowptr[warp + 1];
    float4 acc = make_float4(0.f, 0.f, 0.f, 0.f);
    int j = beg;
    for (; j + 1 < end; j += 2) {
        int s0 = __ldg(&g_col[j]);
        int s1 = __ldg(&g_col[j + 1]);
        float4 v0 = *reinterpret_cast<const float4*>(hin + (size_t)s0 * DD + lane * 4);
        float4 v1 = *reinterpret_cast<const float4*>(hin + (size_t)s1 * DD + lane * 4);
        acc.x += v0.x; acc.y += v0.y; acc.z += v0.z; acc.w += v0.w;
        acc.x += v1.x; acc.y += v1.y; acc.z += v1.z; acc.w += v1.w;
    }
    if (j < end) {
        int s0 = __ldg(&g_col[j]);
        float4 v0 = *reinterpret_cast<const float4*>(hin + (size_t)s0 * DD + lane * 4);
        acc.x += v0.x; acc.y += v0.y; acc.z += v0.z; acc.w += v0.w;
    }
    float id = g_invdeg[warp];
    acc.x *= id; acc.y *= id; acc.z *= id; acc.w *= id;
    uint2 uh, ul;
    split2(acc.x, acc.y, uh.x, ul.x);
    split2(acc.z, acc.w, uh.y, ul.y);
    *(uint2*)(g_ahi + (size_t)warp * DD + lane * 4) = uh;
    *(uint2*)(g_alo + (size_t)warp * DD + lane * 4) = ul;
}

// ---------------- weight transpose + bf16 split --------------------------------
__global__ void k_wsplit(const float* __restrict__ Wl, const float* __restrict__ Wr) {
    int idx = blockIdx.x * blockDim.x + threadIdx.x;
    if (idx >= 128 * 256) return;
    int k = idx & 255;
    int n = idx >> 8;
    float w = (k < 128) ? Wl[k * 128 + n] : Wr[(k - 128) * 128 + n];
    __nv_bfloat16 h = __float2bfloat16(w);
    float r = w - __bfloat162float(h);
    g_wt_hi[n * 256 + k] = h;
    g_wt_lo[n * 256 + k] = __float2bfloat16(r);
}

// ---------------- HMMA GEMM + bias + LayerNorm + ELU / L2-norm -----------------
// D[128x128] = concat(agg, h)[128 x 256] @ W^T  via 3-term bf16 split (mma.sync)
#define AS_HI 0
#define AS_LO 16384
#define WS_HI 32768
#define WS_LO 49152
#define SM_TOTAL 65536
#define SW128X(o) ((o) ^ (((o) >> 3) & 0x70))

__global__ __launch_bounds__(256, 1)
void k_gemm_mma(const __nv_bfloat16* __restrict__ Ahi, const __nv_bfloat16* __restrict__ Alo,
                const __nv_bfloat16* __restrict__ Xhi, const __nv_bfloat16* __restrict__ Xlo,
                const float* __restrict__ bl, const float* __restrict__ gg,
                const float* __restrict__ bb,
                float* __restrict__ out,
                __nv_bfloat16* __restrict__ ohi, __nv_bfloat16* __restrict__ olo,
                int mode)
{
    extern __shared__ char smem[];
    uint32_t sb = smem_u32(smem);
    int tid = threadIdx.x;
    int wid = tid >> 5;
    int lane = tid & 31;
    int row0 = blockIdx.x * 128;

    int m0 = (wid & 3) * 32;
    int n0 = (wid >> 2) * 64;
    int t = lane & 3, g = lane >> 2;

    float acc[2][8][4];
#pragma unroll
    for (int mi = 0; mi < 2; mi++)
#pragma unroll
        for (int ni = 0; ni < 8; ni++)
#pragma unroll
            for (int q = 0; q < 4; q++) acc[mi][ni][q] = 0.f;

    // ldmatrix per-lane address components
    uint32_t swzm = (uint32_t)(lane & 7) << 4;
    uint32_t a_row = m0 + (lane & 7) + ((lane >> 3) & 1) * 8;
    uint32_t a_kb = ((lane >> 4) & 1) * 16;
    uint32_t aoff[2] = { a_row * 128u, (a_row + 16u) * 128u };
    uint32_t j = lane >> 3;
    uint32_t b_kb = (j & 1) * 16;
    uint32_t b_row = n0 + (j >> 1) * 8 + (lane & 7);
    uint32_t boff[4];
#pragma unroll
    for (int p = 0; p < 4; p++) boff[p] = (b_row + p * 16u) * 128u;

    // gmem->smem staging mapping
    int srow = tid >> 1;
    int shf = tid & 1;
    int grow = row0 + srow;
    bool rok = grow < NN;

    for (int c = 0; c < 4; c++) {
        if (c) __syncthreads();
        // A tiles (agg for c<2, hin for c>=2), k-offset within the 128-k array
        const __nv_bfloat16* ah = (c < 2) ? Ahi : Xhi;
        const __nv_bfloat16* al = (c < 2) ? Alo : Xlo;
        int koff = (c & 1) * 64 + shf * 32;
        uint4 vh[4], vl[4], wh[4], wl[4];
        if (rok) {
            const uint4* ph = (const uint4*)(ah + (size_t)grow * 128 + koff);
            const uint4* pl = (const uint4*)(al + (size_t)grow * 128 + koff);
#pragma unroll
            for (int q = 0; q < 4; q++) { vh[q] = ph[q]; vl[q] = pl[q]; }
        } else {
#pragma unroll
            for (int q = 0; q < 4; q++) {
                vh[q] = make_uint4(0, 0, 0, 0);
                vl[q] = make_uint4(0, 0, 0, 0);
            }
        }
        {
            const uint4* pwh = (const uint4*)(g_wt_hi + srow * 256 + c * 64 + shf * 32);
            const uint4* pwl = (const uint4*)(g_wt_lo + srow * 256 + c * 64 + shf * 32);
#pragma unroll
            for (int q = 0; q < 4; q++) { wh[q] = pwh[q]; wl[q] = pwl[q]; }
        }
        uint32_t rb = (uint32_t)srow * 128u;
        uint32_t sm = (uint32_t)(srow & 7) << 4;
#pragma unroll
        for (int q = 0; q < 4; q++) {
            uint32_t off = rb + (((uint32_t)(shf * 64 + q * 16)) ^ sm);
            *(uint4*)(smem + AS_HI + off) = vh[q];
            *(uint4*)(smem + AS_LO + off) = vl[q];
            *(uint4*)(smem + WS_HI + off) = wh[q];
            *(uint4*)(smem + WS_LO + off) = wl[q];
        }
        __syncthreads();

#pragma unroll
        for (int ks = 0; ks < 4; ks++) {
            uint32_t kxa = ((uint32_t)(ks * 32) + a_kb) ^ swzm;
            uint32_t kxb = ((uint32_t)(ks * 32) + b_kb) ^ swzm;
            uint32_t ahr[2][4], alr[2][4], bhr[4][4], blr[4][4];
#pragma unroll
            for (int mi = 0; mi < 2; mi++) {
                ldm_x4(ahr[mi], sb + AS_HI + aoff[mi] + kxa);
                ldm_x4(alr[mi], sb + AS_LO + aoff[mi] + kxa);
            }
#pragma unroll
            for (int p = 0; p < 4; p++) {
                ldm_x4(bhr[p], sb + WS_HI + boff[p] + kxb);
                ldm_x4(blr[p], sb + WS_LO + boff[p] + kxb);
            }
#pragma unroll
            for (int mi = 0; mi < 2; mi++) {
#pragma unroll
                for (int p = 0; p < 4; p++) {
                    mma16816(acc[mi][2 * p],     ahr[mi], bhr[p][0], bhr[p][1]);
                    mma16816(acc[mi][2 * p],     ahr[mi], blr[p][0], blr[p][1]);
                    mma16816(acc[mi][2 * p],     alr[mi], bhr[p][0], bhr[p][1]);
                    mma16816(acc[mi][2 * p + 1], ahr[mi], bhr[p][2], bhr[p][3]);
                    mma16816(acc[mi][2 * p + 1], ahr[mi], blr[p][2], blr[p][3]);
                    mma16816(acc[mi][2 * p + 1], alr[mi], bhr[p][2], bhr[p][3]);
                }
            }
        }
    }
    __syncthreads();   // tiles dead; smem reused for reductions

    // ---- epilogue ----
    const float2* bl2 = (const float2*)bl;
    const float2* g2 = (const float2*)gg;
    const float2* b2 = (const float2*)bb;
    float2 blv[8], gv[8], bv[8];
#pragma unroll
    for (int ni = 0; ni < 8; ni++) {
        int cp = n0 / 2 + ni * 4 + t;
        blv[ni] = __ldg(&bl2[cp]);
        gv[ni] = __ldg(&g2[cp]);
        bv[ni] = __ldg(&b2[cp]);
    }
    float s1[4] = {0, 0, 0, 0}, s2[4] = {0, 0, 0, 0};
#pragma unroll
    for (int mi = 0; mi < 2; mi++)
#pragma unroll
        for (int ni = 0; ni < 8; ni++) {
            float a0 = acc[mi][ni][0] + blv[ni].x;
            float a1 = acc[mi][ni][1] + blv[ni].y;
            float a2 = acc[mi][ni][2] + blv[ni].x;
            float a3 = acc[mi][ni][3] + blv[ni].y;
            acc[mi][ni][0] = a0; acc[mi][ni][1] = a1;
            acc[mi][ni][2] = a2; acc[mi][ni][3] = a3;
            s1[2 * mi] += a0 + a1;       s2[2 * mi] += a0 * a0 + a1 * a1;
            s1[2 * mi + 1] += a2 + a3;   s2[2 * mi + 1] += a2 * a2 + a3 * a3;
        }
#pragma unroll
    for (int q = 0; q < 4; q++) {
        s1[q] += __shfl_xor_sync(0xffffffffu, s1[q], 1);
        s1[q] += __shfl_xor_sync(0xffffffffu, s1[q], 2);
        s2[q] += __shfl_xor_sync(0xffffffffu, s2[q], 1);
        s2[q] += __shfl_xor_sync(0xffffffffu, s2[q], 2);
    }
    float2* red = (float2*)smem;            // [2][128]
    int hh = wid >> 2;
    int R[4] = { m0 + g, m0 + 8 + g, m0 + 16 + g, m0 + 24 + g };
    if (t == 0) {
#pragma unroll
        for (int q = 0; q < 4; q++) red[hh * 128 + R[q]] = make_float2(s1[q], s2[q]);
    }
    __syncthreads();
    float mu[4], rs[4];
#pragma unroll
    for (int q = 0; q < 4; q++) {
        float2 o = red[(1 - hh) * 128 + R[q]];
        float t1 = s1[q] + o.x, t2 = s2[q] + o.y;
        float m = t1 * (1.0f / 128.0f);
        float var = t2 * (1.0f / 128.0f) - m * m;
        mu[q] = m;
        rs[q] = rsqrtf(var + 1e-5f);
    }
    float qs[4] = {0, 0, 0, 0};
#pragma unroll
    for (int mi = 0; mi < 2; mi++)
#pragma unroll
        for (int ni = 0; ni < 8; ni++) {
            float y0 = (acc[mi][ni][0] - mu[2 * mi]) * rs[2 * mi] * gv[ni].x + bv[ni].x;
            float y1 = (acc[mi][ni][1] - mu[2 * mi]) * rs[2 * mi] * gv[ni].y + bv[ni].y;
            float y2 = (acc[mi][ni][2] - mu[2 * mi + 1]) * rs[2 * mi + 1] * gv[ni].x + bv[ni].x;
            float y3 = (acc[mi][ni][3] - mu[2 * mi + 1]) * rs[2 * mi + 1] * gv[ni].y + bv[ni].y;
            if (mode == 0) {
                y0 = (y0 > 0.f) ? y0 : expm1f(y0);
                y1 = (y1 > 0.f) ? y1 : expm1f(y1);
                y2 = (y2 > 0.f) ? y2 : expm1f(y2);
                y3 = (y3 > 0.f) ? y3 : expm1f(y3);
            } else {
                qs[2 * mi] += y0 * y0 + y1 * y1;
                qs[2 * mi + 1] += y2 * y2 + y3 * y3;
            }
            acc[mi][ni][0] = y0; acc[mi][ni][1] = y1;
            acc[mi][ni][2] = y2; acc[mi][ni][3] = y3;
        }
    float sc[4] = {1.f, 1.f, 1.f, 1.f};
    if (mode == 1) {
#pragma unroll
        for (int q = 0; q < 4; q++) {
            qs[q] += __shfl_xor_sync(0xffffffffu, qs[q], 1);
            qs[q] += __shfl_xor_sync(0xffffffffu, qs[q], 2);
        }
        float* red2 = (float*)(smem + 2048);
        if (t == 0) {
#pragma unroll
            for (int q = 0; q < 4; q++) red2[hh * 128 + R[q]] = qs[q];
        }
        __syncthreads();
#pragma unroll
        for (int q = 0; q < 4; q++) {
            float tot = qs[q] + red2[(1 - hh) * 128 + R[q]];
            sc[q] = 1.0f / fmaxf(sqrtf(tot), 1e-12f);
        }
    }
    // stores
#pragma unroll
    for (int mi = 0; mi < 2; mi++) {
        int rA = row0 + R[2 * mi];
        int rB = row0 + R[2 * mi + 1];
#pragma unroll
        for (int ni = 0; ni < 8; ni++) {
            int col = n0 + ni * 8 + t * 2;
            float y0 = acc[mi][ni][0] * sc[2 * mi];
            float y1 = acc[mi][ni][1] * sc[2 * mi];
            float y2 = acc[mi][ni][2] * sc[2 * mi + 1];
            float y3 = acc[mi][ni][3] * sc[2 * mi + 1];
            if (rA < NN) {
                *(float2*)(out + (size_t)rA * 128 + col) = make_float2(y0, y1);
                if (mode == 0) {
                    uint32_t h, l;
                    split2(y0, y1, h, l);
                    *(uint32_t*)(ohi + (size_t)rA * 128 + col) = h;
                    *(uint32_t*)(olo + (size_t)rA * 128 + col) = l;
                }
            }
            if (rB < NN) {
                *(float2*)(out + (size_t)rB * 128 + col) = make_float2(y2, y3);
                if (mode == 0) {
                    uint32_t h, l;
                    split2(y2, y3, h, l);
                    *(uint32_t*)(ohi + (size_t)rB * 128 + col) = h;
                    *(uint32_t*)(olo + (size_t)rB * 128 + col) = l;
                }
            }
        }
    }
}

// ---------------- launch --------------------------------------------------------
extern "C" void kernel_launch(void* const* d_in, const int* in_sizes, int n_in,
                              void* d_out, int out_size) {
    const float* x = (const float*)d_in[0];
    const void* ei = d_in[1];

    float* buf0; cudaGetSymbolAddress((void**)&buf0, g_buf0);
    float* buf1; cudaGetSymbolAddress((void**)&buf1, g_buf1);
    __nv_bfloat16 *h0hi, *h0lo, *h1hi, *h1lo, *ahi, *alo;
    cudaGetSymbolAddress((void**)&h0hi, g_h0hi);
    cudaGetSymbolAddress((void**)&h0lo, g_h0lo);
    cudaGetSymbolAddress((void**)&h1hi, g_h1hi);
    cudaGetSymbolAddress((void**)&h1lo, g_h1lo);
    cudaGetSymbolAddress((void**)&ahi, g_ahi);
    cudaGetSymbolAddress((void**)&alo, g_alo);

    cudaFuncSetAttribute(k_gemm_mma, cudaFuncAttributeMaxDynamicSharedMemorySize, SM_TOTAL);

    const int TB = 256;
    const int EBLK = (EE + TB - 1) / TB;
    const int NBLK = (NN + TB - 1) / TB;
    const int SCAN_NB = (NN + 1023) / 1024;

    k_probe<<<1, 256>>>((const long long*)ei);
    k_convert<<<EBLK, TB>>>(ei);

    k_zero_cnt<<<NBLK, TB>>>();
    k_hist<<<EBLK, TB>>>();
    k_scan1<<<SCAN_NB, 1024>>>();
    k_scan2<<<1, 32>>>(SCAN_NB);
    k_scan3<<<NBLK, TB>>>();
    k_scatter<<<EBLK, TB>>>();

    k_split_x<<<(NROWS4 + TB - 1) / TB, TB>>>(x, h0hi, h0lo);

    const int AGG_BLK = (NN * 32 + TB - 1) / TB;
    const int GEMM_BLK = (NN + 127) / 128;

    for (int l = 0; l < 3; l++) {
        const float* hin = (l == 0) ? x : ((l == 1) ? buf0 : buf1);
        float* hout = (l == 0) ? buf0 : ((l == 1) ? buf1 : (float*)d_out);
        const __nv_bfloat16* xh = (l == 1) ? h1hi : h0hi;
        const __nv_bfloat16* xl = (l == 1) ? h1lo : h0lo;
        __nv_bfloat16* oh = (l == 0) ? h1hi : h0hi;
        __nv_bfloat16* ol = (l == 0) ? h1lo : h0lo;
        const float* Wl = (const float*)d_in[2 + 5 * l + 0];
        const float* bl = (const float*)d_in[2 + 5 * l + 1];
        const float* Wr = (const float*)d_in[2 + 5 * l + 2];
        const float* gg = (const float*)d_in[2 + 5 * l + 3];
        const float* bb = (const float*)d_in[2 + 5 * l + 4];

        k_wsplit<<<128, 256>>>(Wl, Wr);
        k_aggregate<<<AGG_BLK, TB>>>(hin);
        k_gemm_mma<<<GEMM_BLK, TB, SM_TOTAL>>>(ahi, alo, xh, xl, bl, gg, bb,
                                               hout, oh, ol, (l < 2) ? 0 : 1);
    }
}